// round 3
// baseline (speedup 1.0000x reference)
#include <cuda_runtime.h>
#include <cstdint>

#define N_GRAPHS 4096

// Invariant: zero at module load AND at the end of every kernel_launch
// (the finalizing block resets them). Graph-replay safe.
__device__ float        g_sums[N_GRAPHS];
__device__ float        g_counts[N_GRAPHS];
__device__ unsigned int g_done;

__global__ void fused_mean_kernel(const float* __restrict__ x,
                                  const void* __restrict__ batch,
                                  float* __restrict__ out,
                                  int n, int dfeat, int nblocks) {
    __shared__ int   s_is64;
    __shared__ bool  s_last;

    // ---- per-block dtype detect (L2-hot, ~1 line) ----
    if (threadIdx.x == 0) {
        const int* b32 = (const int*)batch;
        int base = (n / 2) & ~1;
        if (base + 7 >= n) base = 0;
        bool odd_zero = (b32[base + 1] == 0) && (b32[base + 3] == 0) &&
                        (b32[base + 5] == 0) && (b32[base + 7] == 0);
        bool even_nz  = (b32[base] != 0) && (b32[base + 2] != 0);
        s_is64 = (odd_zero && even_nz) ? 1 : 0;
    }
    __syncthreads();
    const int is64 = s_is64;

    // ---- warp-segmented accumulate ----
    int i = blockIdx.x * blockDim.x + threadIdx.x;
    int lane = threadIdx.x & 31;

    float v = 0.0f, c = 0.0f;
    int seg = -1;
    if (i < n) {
        v = __ldg(&x[(size_t)i * (size_t)dfeat]);
        seg = is64 ? (int)__ldg(&((const long long*)batch)[i])
                   : __ldg(&((const int*)batch)[i]);
        c = 1.0f;
    }

    const unsigned mask = 0xffffffffu;
    #pragma unroll
    for (int d = 1; d < 32; d <<= 1) {
        float v2 = __shfl_down_sync(mask, v, d);
        float c2 = __shfl_down_sync(mask, c, d);
        int   s2 = __shfl_down_sync(mask, seg, d);
        if (lane + d < 32 && s2 == seg) { v += v2; c += c2; }
    }

    int seg_up = __shfl_up_sync(mask, seg, 1);
    bool head = (lane == 0) || (seg_up != seg);
    if (i < n && head && seg >= 0 && seg < N_GRAPHS) {
        atomicAdd(&g_sums[seg], v);
        atomicAdd(&g_counts[seg], c);
    }

    // ---- last-block finalize (threadfence + counter) ----
    __threadfence();
    __syncthreads();
    if (threadIdx.x == 0) {
        unsigned int done = atomicAdd(&g_done, 1u);
        s_last = (done == (unsigned int)(nblocks - 1));
    }
    __syncthreads();

    if (s_last) {
        for (int g = threadIdx.x; g < N_GRAPHS; g += blockDim.x) {
            float s   = __ldcg(&g_sums[g]);     // L2 read (atomics landed in L2)
            float cnt = __ldcg(&g_counts[g]);
            out[g] = (cnt > 0.0f) ? (s / cnt) : 0.0f;
            g_sums[g]   = 0.0f;                 // restore invariant for next replay
            g_counts[g] = 0.0f;
        }
        __syncthreads();
        if (threadIdx.x == 0) g_done = 0u;
    }
}

extern "C" void kernel_launch(void* const* d_in, const int* in_sizes, int n_in,
                              void* d_out, int out_size) {
    // Identify inputs by element count: x is the largest, batch the smallest.
    int xi = 0, bi = 0;
    for (int k = 1; k < n_in; k++) {
        if (in_sizes[k] > in_sizes[xi]) xi = k;
        if (in_sizes[k] < in_sizes[bi]) bi = k;
    }
    const float* x     = (const float*)d_in[xi];
    const void*  batch = d_in[bi];
    float* out = (float*)d_out;

    int n = in_sizes[bi];
    int dfeat = in_sizes[xi] / n;

    int threads = 256;
    int blocks = (n + threads - 1) / threads;
    fused_mean_kernel<<<blocks, threads>>>(x, batch, out, n, dfeat, blocks);
}

// round 4
// speedup vs baseline: 1.3505x; 1.3505x over previous
#include <cuda_runtime.h>
#include <cstdint>

#define N_GRAPHS 4096
#define CHUNKS   4          // 32-node chunks per warp
#define THREADS  256

// Invariant: zero at module load AND after every finalize_kernel.
__device__ float g_sums[N_GRAPHS];
__device__ float g_counts[N_GRAPHS];

__global__ void accum_kernel(const float* __restrict__ x,
                             const void* __restrict__ batch,
                             int n, int dfeat) {
    __shared__ int s_is64;
    // Per-block dtype detect (int64 little-endian view shows [v,0,v,0,...]).
    if (threadIdx.x == 0) {
        const int* b32 = (const int*)batch;
        int base = (n / 2) & ~1;
        if (base + 7 >= n) base = 0;
        bool odd_zero = (b32[base + 1] == 0) && (b32[base + 3] == 0) &&
                        (b32[base + 5] == 0) && (b32[base + 7] == 0);
        bool even_nz  = (b32[base] != 0) && (b32[base + 2] != 0);
        s_is64 = (odd_zero && even_nz) ? 1 : 0;
    }
    __syncthreads();
    const int is64 = s_is64;

    const int lane = threadIdx.x & 31;
    const long long warp_global =
        (long long)((blockIdx.x * blockDim.x + threadIdx.x) >> 5);
    const long long base = warp_global * (32LL * CHUNKS);
    const unsigned mask = 0xffffffffu;

    // Front-batched loads: 4 x-values + 4 batch-values in flight (MLP~8).
    float v[CHUNKS];
    int   seg[CHUNKS];
    #pragma unroll
    for (int c = 0; c < CHUNKS; c++) {
        long long i = base + (long long)c * 32 + lane;
        if (i < n) {
            seg[c] = is64 ? (int)__ldg(&((const long long*)batch)[i])
                          : __ldg(&((const int*)batch)[i]);
            v[c]   = __ldg(&x[(size_t)i * (size_t)dfeat]);
        } else {
            seg[c] = -1;
            v[c]   = 0.0f;
        }
    }

    #pragma unroll
    for (int c = 0; c < CHUNKS; c++) {
        int   s  = seg[c];
        float vv = v[c];

        // Head lanes: first lane of each same-segment run.
        int s_up = __shfl_up_sync(mask, s, 1);
        bool head = (lane == 0) || (s_up != s);
        unsigned hm = __ballot_sync(mask, head);

        // Segmented suffix sum using only the head mask (no seg shuffles):
        // lane may absorb lane+d iff no head lies in (lane, lane+d].
        #pragma unroll
        for (int d = 1; d < 32; d <<= 1) {
            float v2 = __shfl_down_sync(mask, vv, d);
            unsigned between = (hm >> (lane + 1)) & ((1u << d) - 1u);
            if ((lane + d < 32) && (between == 0u)) vv += v2;
        }

        if (head && s >= 0 && s < N_GRAPHS) {
            // Run length = distance to next head (or end of warp).
            unsigned above = hm >> 1;               // heads at lanes > ...
            unsigned nxt = (lane < 31) ? (hm >> (lane + 1)) : 0u;
            int run = nxt ? __ffs(nxt) : (32 - lane);
            (void)above;
            atomicAdd(&g_sums[s], vv);
            atomicAdd(&g_counts[s], (float)run);
        }
    }
}

__global__ void finalize_kernel(float* __restrict__ out) {
    int i = blockIdx.x * blockDim.x + threadIdx.x;
    if (i < N_GRAPHS) {
        float cnt = g_counts[i];
        out[i] = (cnt > 0.0f) ? (g_sums[i] / cnt) : 0.0f;
        g_sums[i]   = 0.0f;     // restore invariant for next graph replay
        g_counts[i] = 0.0f;
    }
}

extern "C" void kernel_launch(void* const* d_in, const int* in_sizes, int n_in,
                              void* d_out, int out_size) {
    // Identify inputs by element count: x largest, batch smallest.
    int xi = 0, bi = 0;
    for (int k = 1; k < n_in; k++) {
        if (in_sizes[k] > in_sizes[xi]) xi = k;
        if (in_sizes[k] < in_sizes[bi]) bi = k;
    }
    const float* x     = (const float*)d_in[xi];
    const void*  batch = d_in[bi];
    float* out = (float*)d_out;

    int n = in_sizes[bi];
    int dfeat = in_sizes[xi] / n;

    int elems_per_block = THREADS * CHUNKS;   // 1024
    int blocks = (n + elems_per_block - 1) / elems_per_block;
    accum_kernel<<<blocks, THREADS>>>(x, batch, n, dfeat);

    finalize_kernel<<<(N_GRAPHS + 255) / 256, 256>>>(out);
}